// round 14
// baseline (speedup 1.0000x reference)
#include <cuda_runtime.h>
#include <cuda_bf16.h>
#include <cuda_fp16.h>
#include <cstdint>

#define NROWS 8192

// ---------------- scratch (__device__ globals; no allocation allowed) ----------
__device__ __align__(16) float g_Y[NROWS * 128];
__device__ __align__(16) float g_T[NROWS * 128];
__device__ __align__(16) float g_Z[NROWS * 128];
__device__ __align__(16) float g_P[2 * NROWS * 128];                  // split-K partials (X@W only)
__device__ __align__(16) __half g_S16[(size_t)NROWS * NROWS];         // fp16(S), 128 MB
__device__ __align__(16) __nv_bfloat16 g_Ahi[NROWS * 512];            // row acts, bf16 hi
__device__ __align__(16) __nv_bfloat16 g_Alo[NROWS * 512];            // row acts, bf16 lo
__device__ __align__(16) __half g_B16a[128 * NROWS];                  // transposed acts fp16 (ping)
__device__ __align__(16) __half g_B16b[128 * NROWS];                  // transposed acts fp16 (pong)
__device__ __align__(16) __nv_bfloat16 g_Whi[128 * 512];
__device__ __align__(16) __nv_bfloat16 g_Wlo[128 * 512];

__device__ __forceinline__ uint32_t smem_u32(const void* p) {
    uint32_t a;
    asm("{ .reg .u64 t; cvta.to.shared.u64 t, %1; cvt.u32.u64 %0, t; }" : "=r"(a) : "l"(p));
    return a;
}

#define LDSM_X4(r, addr)                                                        \
    asm volatile("ldmatrix.sync.aligned.m8n8.x4.shared.b16 {%0,%1,%2,%3}, [%4];"\
                 : "=r"((r)[0]), "=r"((r)[1]), "=r"((r)[2]), "=r"((r)[3])       \
                 : "r"(addr))

#define MMA_BF16(d, a, b)                                                       \
    asm volatile("mma.sync.aligned.m16n8k16.row.col.f32.bf16.bf16.f32 "         \
                 "{%0,%1,%2,%3}, {%4,%5,%6,%7}, {%8,%9}, {%0,%1,%2,%3};"        \
                 : "+f"((d)[0]), "+f"((d)[1]), "+f"((d)[2]), "+f"((d)[3])       \
                 : "r"((a)[0]), "r"((a)[1]), "r"((a)[2]), "r"((a)[3]),          \
                   "r"((b)[0]), "r"((b)[1]))

#define MMA_FP16(d, a, b)                                                       \
    asm volatile("mma.sync.aligned.m16n8k16.row.col.f32.f16.f16.f32 "           \
                 "{%0,%1,%2,%3}, {%4,%5,%6,%7}, {%8,%9}, {%0,%1,%2,%3};"        \
                 : "+f"((d)[0]), "+f"((d)[1]), "+f"((d)[2]), "+f"((d)[3])       \
                 : "r"((a)[0]), "r"((a)[1]), "r"((a)[2]), "r"((a)[3]),          \
                   "r"((b)[0]), "r"((b)[1]))

#define CP16(s, g)                                                              \
    asm volatile("cp.async.cg.shared.global [%0], [%1], 16;"                    \
                 :: "r"(s), "l"(g) : "memory")
#define CP_COMMIT() asm volatile("cp.async.commit_group;" ::: "memory")
#define CP_WAIT(n)  asm volatile("cp.async.wait_group %0;" :: "n"(n) : "memory")

__device__ __forceinline__ void split2(float a, float b, uint32_t& hi, uint32_t& lo) {
    __nv_bfloat162 H, L;
    H.x = __float2bfloat16(a);
    H.y = __float2bfloat16(b);
    L.x = __float2bfloat16(a - __bfloat162float(H.x));
    L.y = __float2bfloat16(b - __bfloat162float(H.y));
    hi = *reinterpret_cast<uint32_t*>(&H);
    lo = *reinterpret_cast<uint32_t*>(&L);
}

// ---------------- fp32 -> fp16 single convert (for S) --------------------------
__global__ void split_s16_k(const float* __restrict__ in, __half* __restrict__ o)
{
    size_t i = ((size_t)blockIdx.x * 256 + threadIdx.x) * 8;
    float4 v0 = *(const float4*)(in + i);
    float4 v1 = *(const float4*)(in + i + 4);
    __half2 h[4];
    h[0] = __floats2half2_rn(v0.x, v0.y);
    h[1] = __floats2half2_rn(v0.z, v0.w);
    h[2] = __floats2half2_rn(v1.x, v1.y);
    h[3] = __floats2half2_rn(v1.z, v1.w);
    *(uint4*)(o + i) = *reinterpret_cast<uint4*>(h);
}

// ---------------- row-major bf16 split (for X) ---------------------------------
__global__ void split_k(const float* __restrict__ in, __nv_bfloat16* __restrict__ ohi,
                        __nv_bfloat16* __restrict__ olo)
{
    size_t i = ((size_t)blockIdx.x * 256 + threadIdx.x) * 8;
    float4 v0 = *(const float4*)(in + i);
    float4 v1 = *(const float4*)(in + i + 4);
    uint4 H, L;
    split2(v0.x, v0.y, H.x, L.x);
    split2(v0.z, v0.w, H.y, L.y);
    split2(v1.x, v1.y, H.z, L.z);
    split2(v1.z, v1.w, H.w, L.w);
    *(uint4*)(ohi + i) = H;
    *(uint4*)(olo + i) = L;
}

// ---------------- transpose + bf16 split (for W) -------------------------------
__global__ void convt_k(const float* __restrict__ in, __nv_bfloat16* __restrict__ ohi,
                        __nv_bfloat16* __restrict__ olo, int R, int C)
{
    __shared__ float tile[32][33];
    const int bx = blockIdx.x * 32, by = blockIdx.y * 32;
    const int tx = threadIdx.x, ty = threadIdx.y;
#pragma unroll
    for (int i = 0; i < 32; i += 8)
        tile[ty + i][tx] = in[(size_t)(by + ty + i) * C + bx + tx];
    __syncthreads();
#pragma unroll
    for (int i = 0; i < 32; i += 8) {
        float v = tile[tx][ty + i];
        __nv_bfloat16 h = __float2bfloat16(v);
        size_t o = (size_t)(bx + ty + i) * R + by + tx;
        ohi[o] = h;
        olo[o] = __float2bfloat16(v - __bfloat162float(h));
    }
}

// ---------------- combine NP split-K partials + transpose fp16 convert ---------
// (used after X@W GEMMs only)
template <int NP>
__global__ void combine_t16_k(const float* __restrict__ P, size_t pstride,
                              float* __restrict__ Trm,
                              __half* __restrict__ o16, int R, int C)
{
    __shared__ float tile[32][33];
    const int bx = blockIdx.x * 32, by = blockIdx.y * 32;
    const int tx = threadIdx.x, ty = threadIdx.y;
#pragma unroll
    for (int i = 0; i < 32; i += 8) {
        size_t idx = (size_t)(by + ty + i) * C + bx + tx;
        float v = 0.f;
#pragma unroll
        for (int p = 0; p < NP; p++) v += P[idx + p * pstride];
        Trm[idx] = v;
        tile[ty + i][tx] = v;
    }
    __syncthreads();
#pragma unroll
    for (int i = 0; i < 32; i += 8) {
        float v = tile[tx][ty + i];
        o16[(size_t)(bx + ty + i) * R + by + tx] = __float2half(v);
    }
}

// ================== bf16 3-pass GEMM (X@W path), BM=128, 256 thr, split-K ======
template <int BN, int D>
__global__ void __launch_bounds__(256)
tgemm3_k(const __nv_bfloat16* __restrict__ Ahi, const __nv_bfloat16* __restrict__ Alo,
         int lda,
         const __nv_bfloat16* __restrict__ Bhi, const __nv_bfloat16* __restrict__ Blo,
         int ldb, int Ktot, float* __restrict__ C)
{
    extern __shared__ char sm[];
    constexpr int WN = BN / 4;
    constexpr int NT = WN / 8;
    constexpr int ASPL = 128 * 128;
    constexpr int BSPL = BN * 128;
    constexpr int STAGE = 2 * ASPL + 2 * BSPL;

    const int tid = threadIdx.x, wid = tid >> 5, lid = tid & 31;
    const int wm = wid & 1, wn = wid >> 1;
    const int m0 = blockIdx.x * 128;
    const int kslice = Ktot / gridDim.y;
    const int kbase = blockIdx.y * kslice;
    const int nk = kslice / 64;
    float* Cout = C + (size_t)blockIdx.y * (gridDim.x * 128) * BN;
    const uint32_t smb = smem_u32(sm);

    const int ldrow = tid >> 3, ldc = tid & 7;
    const int arl = lid & 15, ahf = lid >> 4;
    const int brl = (lid & 7) + ((lid >> 4) << 3);
    const int bhf = (lid >> 3) & 1;
    const int asw = arl & 7, bsw = lid & 7;

    float acc[2][2][NT][4];
#pragma unroll
    for (int s = 0; s < 2; s++)
#pragma unroll
        for (int mt = 0; mt < 2; mt++)
#pragma unroll
            for (int nt = 0; nt < NT; nt++)
#pragma unroll
                for (int j = 0; j < 4; j++) acc[s][mt][nt][j] = 0.f;

    auto issue = [&](int ch, int buf) {
        const uint32_t sb = smb + buf * STAGE;
        const int kg = kbase + ch * 64;
#pragma unroll
        for (int it = 0; it < 4; it++) {
            const int row = ldrow + 32 * it;
            const size_t go = (size_t)(m0 + row) * lda + kg + ldc * 8;
            const uint32_t so = sb + row * 128 + ((ldc ^ (row & 7)) << 4);
            CP16(so, (const void*)(Ahi + go));
            CP16(so + ASPL, (const void*)(Alo + go));
        }
#pragma unroll
        for (int it = 0; it < BN / 32; it++) {
            const int row = ldrow + 32 * it;
            const size_t go = (size_t)row * ldb + kg + ldc * 8;
            const uint32_t so = sb + 2 * ASPL + row * 128 + ((ldc ^ (row & 7)) << 4);
            CP16(so, (const void*)(Bhi + go));
            CP16(so + BSPL, (const void*)(Blo + go));
        }
    };

#pragma unroll
    for (int s = 0; s < D - 1; s++) {
        if (s < nk) issue(s, s);
        CP_COMMIT();
    }

    for (int i = 0; i < nk; i++) {
        CP_WAIT(D - 2);
        __syncthreads();
        if (i + D - 1 < nk) issue(i + D - 1, (i + D - 1) % D);
        CP_COMMIT();

        const uint32_t cab = smb + (i % D) * STAGE;
        const uint32_t cbb = cab + 2 * ASPL;

#pragma unroll
        for (int ks = 0; ks < 4; ks++) {
            uint32_t bH[NT][2], bL[NT][2];
#pragma unroll
            for (int p = 0; p < NT / 2; p++) {
                const uint32_t bo = (uint32_t)((wn * WN + p * 16 + brl) * 128)
                                  + (uint32_t)(((ks * 2 + bhf) ^ bsw) << 4);
                uint32_t t[4];
                LDSM_X4(t, cbb + bo);
                bH[2 * p][0] = t[0]; bH[2 * p][1] = t[1];
                bH[2 * p + 1][0] = t[2]; bH[2 * p + 1][1] = t[3];
                LDSM_X4(t, cbb + BSPL + bo);
                bL[2 * p][0] = t[0]; bL[2 * p][1] = t[1];
                bL[2 * p + 1][0] = t[2]; bL[2 * p + 1][1] = t[3];
            }
#pragma unroll
            for (int sub = 0; sub < 2; sub++) {
                uint32_t aH[2][4], aL[2][4];
#pragma unroll
                for (int mt = 0; mt < 2; mt++) {
                    const uint32_t ao = (uint32_t)((sub * 64 + wm * 32 + mt * 16 + arl) * 128)
                                      + (uint32_t)(((ks * 2 + ahf) ^ asw) << 4);
                    LDSM_X4(aH[mt], cab + ao);
                    LDSM_X4(aL[mt], cab + ASPL + ao);
                }
#pragma unroll
                for (int mt = 0; mt < 2; mt++)
#pragma unroll
                    for (int nt = 0; nt < NT; nt++) {
                        MMA_BF16(acc[sub][mt][nt], aH[mt], bH[nt]);
                        MMA_BF16(acc[sub][mt][nt], aH[mt], bL[nt]);
                        MMA_BF16(acc[sub][mt][nt], aL[mt], bH[nt]);
                    }
            }
        }
    }

#pragma unroll
    for (int sub = 0; sub < 2; sub++)
#pragma unroll
        for (int mt = 0; mt < 2; mt++)
#pragma unroll
            for (int half = 0; half < 2; half++) {
                const int row = m0 + sub * 64 + wm * 32 + mt * 16 + (lid >> 2) + half * 8;
#pragma unroll
                for (int nt = 0; nt < NT; nt++) {
                    const int col = wn * WN + nt * 8 + (lid & 3) * 2;
                    float2 v = make_float2(acc[sub][mt][nt][half * 2 + 0],
                                           acc[sub][mt][nt][half * 2 + 1]);
                    *(float2*)(Cout + (size_t)row * BN + col) = v;
                }
            }
}

// ====== fp16 1-pass S-GEMM, fused epilogue ====================================
// BM=64, BN-tile=64, 256 thr (8 warps, 2m x 4n, warp tile 32x16), no split-K.
// grid = (M/64, W/64). K = full NROWS.
// EPI=false: C = acc (fp32, width Wd) AND B16out[col][row] = fp16(acc)  (transposed)
// EPI=true : v = h0*Y + h1*T + h2*acc + bias; RELU?; C = v; WSPLIT: zhi/zlo bf16 split
template <bool EPI, bool RELU, bool WSPLIT>
__global__ void __launch_bounds__(256, 2)
tgemmF_k(const __half* __restrict__ A16, int lda,
         const __half* __restrict__ B16, int ldb, int Ktot, int Wd,
         float* __restrict__ C, __half* __restrict__ B16out,
         const float* __restrict__ Ybuf, const float* __restrict__ Tbuf,
         const float* __restrict__ hv, const float* __restrict__ bias,
         __nv_bfloat16* __restrict__ zhi, __nv_bfloat16* __restrict__ zlo)
{
    extern __shared__ char sm[];
    constexpr int D = 6;
    constexpr int ASPL = 64 * 128;      // 8 KB
    constexpr int BSPL = 64 * 128;      // 8 KB
    constexpr int STAGE = ASPL + BSPL;  // 16 KB -> 96 KB total

    const int tid = threadIdx.x, wid = tid >> 5, lid = tid & 31;
    const int wm = wid & 1, wn = wid >> 1;      // 2 m-warps x 4 n-warps
    const int m0 = blockIdx.x * 64;
    const int n0 = blockIdx.y * 64;
    const int nk = Ktot / 64;
    const uint32_t smb = smem_u32(sm);

    const int ldrow = tid >> 3, ldc = tid & 7;  // 0..31 rows per iter
    const int arl = lid & 15, ahf = lid >> 4;
    const int brl = (lid & 7) + ((lid >> 4) << 3);
    const int bhf = (lid >> 3) & 1;
    const int asw = arl & 7, bsw = lid & 7;

    float acc[2][2][4];                 // [mt][nt][4]; warp tile 32x16
#pragma unroll
    for (int mt = 0; mt < 2; mt++)
#pragma unroll
        for (int nt = 0; nt < 2; nt++)
#pragma unroll
            for (int j = 0; j < 4; j++) acc[mt][nt][j] = 0.f;

    auto issue = [&](int ch, int buf) {
        const uint32_t sb = smb + buf * STAGE;
        const int kg = ch * 64;
#pragma unroll
        for (int it = 0; it < 2; it++) {
            const int row = ldrow + 32 * it;
            const size_t goA = (size_t)(m0 + row) * lda + kg + ldc * 8;
            const size_t goB = (size_t)(n0 + row) * ldb + kg + ldc * 8;
            const uint32_t sw = (uint32_t)(row * 128 + ((ldc ^ (row & 7)) << 4));
            CP16(sb + sw, (const void*)(A16 + goA));
            CP16(sb + ASPL + sw, (const void*)(B16 + goB));
        }
    };

#pragma unroll
    for (int s = 0; s < D - 1; s++) {
        if (s < nk) issue(s, s);
        CP_COMMIT();
    }

    for (int i = 0; i < nk; i++) {
        CP_WAIT(D - 2);
        __syncthreads();
        if (i + D - 1 < nk) issue(i + D - 1, (i + D - 1) % D);
        CP_COMMIT();

        const uint32_t cab = smb + (i % D) * STAGE;
        const uint32_t cbb = cab + ASPL;

#pragma unroll
        for (int ks = 0; ks < 4; ks++) {
            uint32_t bF[2][2];
            {
                const uint32_t bo = (uint32_t)((wn * 16 + brl) * 128)
                                  + (uint32_t)(((ks * 2 + bhf) ^ bsw) << 4);
                uint32_t t[4];
                LDSM_X4(t, cbb + bo);
                bF[0][0] = t[0]; bF[0][1] = t[1];
                bF[1][0] = t[2]; bF[1][1] = t[3];
            }
            uint32_t aF[2][4];
#pragma unroll
            for (int mt = 0; mt < 2; mt++) {
                const uint32_t ao = (uint32_t)((wm * 32 + mt * 16 + arl) * 128)
                                  + (uint32_t)(((ks * 2 + ahf) ^ asw) << 4);
                LDSM_X4(aF[mt], cab + ao);
            }
#pragma unroll
            for (int mt = 0; mt < 2; mt++)
#pragma unroll
                for (int nt = 0; nt < 2; nt++)
                    MMA_FP16(acc[mt][nt], aF[mt], bF[nt]);
        }
    }

    // ---- fused epilogue ----
    float c0 = 0.f, c1 = 0.f, c2 = 0.f;
    if (EPI) { c0 = hv[0]; c1 = hv[1]; c2 = hv[2]; }
#pragma unroll
    for (int mt = 0; mt < 2; mt++) {
#pragma unroll
        for (int half = 0; half < 2; half++) {
            const int row = m0 + wm * 32 + mt * 16 + (lid >> 2) + half * 8;
#pragma unroll
            for (int nt = 0; nt < 2; nt++) {
                const int col = n0 + wn * 16 + nt * 8 + (lid & 3) * 2;
                float2 v = make_float2(acc[mt][nt][half * 2 + 0],
                                       acc[mt][nt][half * 2 + 1]);
                const size_t ro = (size_t)row * Wd + col;
                if (EPI) {
                    const float2 y = *(const float2*)(Ybuf + ro);
                    const float2 t = *(const float2*)(Tbuf + ro);
                    const float2 bb = *(const float2*)(bias + col);
                    v.x = c0 * y.x + c1 * t.x + c2 * v.x + bb.x;
                    v.y = c0 * y.y + c1 * t.y + c2 * v.y + bb.y;
                    if (RELU) { v.x = fmaxf(v.x, 0.f); v.y = fmaxf(v.y, 0.f); }
                    *(float2*)(C + ro) = v;
                    if (WSPLIT) {
                        uint32_t H, L;
                        split2(v.x, v.y, H, L);
                        *(uint32_t*)(zhi + ro) = H;
                        *(uint32_t*)(zlo + ro) = L;
                    }
                } else {
                    *(float2*)(C + ro) = v;
                    B16out[(size_t)col * NROWS + row] = __float2half(v.x);
                    B16out[(size_t)(col + 1) * NROWS + row] = __float2half(v.y);
                }
            }
        }
    }
}

// -------------------------------------------------------------------------------
extern "C" void kernel_launch(void* const* d_in, const int* in_sizes, int n_in,
                              void* d_out, int out_size)
{
    (void)in_sizes; (void)n_in; (void)out_size;
    const float* S  = (const float*)d_in[0];
    const float* X  = (const float*)d_in[1];
    const float* W1 = (const float*)d_in[2];
    const float* h1 = (const float*)d_in[3];
    const float* b1 = (const float*)d_in[4];
    const float* W2 = (const float*)d_in[5];
    const float* h2 = (const float*)d_in[6];
    const float* b2 = (const float*)d_in[7];
    const float* W3 = (const float*)d_in[8];
    const float* h3 = (const float*)d_in[9];
    const float* b3 = (const float*)d_in[10];
    float* out = (float*)d_out;

    float *Y, *T, *Z, *P;
    __half *S16, *B16a, *B16b;
    __nv_bfloat16 *Ahi, *Alo, *Whi, *Wlo;
    cudaGetSymbolAddress((void**)&Y, g_Y);
    cudaGetSymbolAddress((void**)&T, g_T);
    cudaGetSymbolAddress((void**)&Z, g_Z);
    cudaGetSymbolAddress((void**)&P, g_P);
    cudaGetSymbolAddress((void**)&S16, g_S16);
    cudaGetSymbolAddress((void**)&B16a, g_B16a);
    cudaGetSymbolAddress((void**)&B16b, g_B16b);
    cudaGetSymbolAddress((void**)&Ahi, g_Ahi);
    cudaGetSymbolAddress((void**)&Alo, g_Alo);
    cudaGetSymbolAddress((void**)&Whi, g_Whi);
    cudaGetSymbolAddress((void**)&Wlo, g_Wlo);

    const size_t PSW = (size_t)NROWS * 128;   // partial stride, BN=128 (X@W)
    const size_t PSN = (size_t)NROWS * 64;    // partial stride, BN=64  (X@W3)

    const int SM3W = 3 * (2 * 16384 + 2 * 16384);  // 196608: bf16 3-pass, BN=128, D=3
    const int SM3N = 4 * (2 * 16384 + 2 * 8192);   // 196608: bf16 3-pass, BN=64,  D=4
    const int SMF  = 6 * (8192 + 8192);            //  98304: fused fp16 S-GEMM, D=6
    cudaFuncSetAttribute(tgemm3_k<128, 3>, cudaFuncAttributeMaxDynamicSharedMemorySize, SM3W);
    cudaFuncSetAttribute(tgemm3_k<64, 4>,  cudaFuncAttributeMaxDynamicSharedMemorySize, SM3N);
    cudaFuncSetAttribute(tgemmF_k<false, false, false>, cudaFuncAttributeMaxDynamicSharedMemorySize, SMF);
    cudaFuncSetAttribute(tgemmF_k<true,  true,  true >, cudaFuncAttributeMaxDynamicSharedMemorySize, SMF);
    cudaFuncSetAttribute(tgemmF_k<true,  false, false>, cudaFuncAttributeMaxDynamicSharedMemorySize, SMF);

    const dim3 tb(32, 8);
    const dim3 gW(NROWS / 128, 2);        // X@W: BM=128, split-K2 (128 CTAs)
    const dim3 gFw(NROWS / 64, 2);        // fused S-GEMM wide: 256 CTAs
    const dim3 gFn(NROWS / 64, 1);        // fused S-GEMM narrow: 128 CTAs

    // one-time converts
    split_s16_k<<<(size_t)NROWS * NROWS / 2048, 256>>>(S, S16);
    split_k<<<NROWS * 512 / 2048, 256>>>(X, Ahi, Alo);

    // ================= Layer 1 =================
    convt_k<<<dim3(4, 16), tb>>>(W1, Whi, Wlo, 512, 128);
    tgemm3_k<128, 3><<<gW, 256, SM3W>>>(Ahi, Alo, 512, Whi, Wlo, 512, 512, P);
    combine_t16_k<2><<<dim3(4, 256), tb>>>(P, PSW, Y, B16a, NROWS, 128);
    tgemmF_k<false, false, false><<<gFw, 256, SMF>>>(S16, NROWS, B16a, NROWS, NROWS, 128,
                                                     T, B16b, nullptr, nullptr, nullptr,
                                                     nullptr, nullptr, nullptr);
    tgemmF_k<true, true, true><<<gFw, 256, SMF>>>(S16, NROWS, B16b, NROWS, NROWS, 128,
                                                  Z, nullptr, Y, T, h1, b1, Ahi, Alo);
    // ================= Layer 2 =================
    convt_k<<<dim3(4, 4), tb>>>(W2, Whi, Wlo, 128, 128);
    tgemm3_k<128, 3><<<gW, 256, SM3W>>>(Ahi, Alo, 128, Whi, Wlo, 128, 128, P);
    combine_t16_k<2><<<dim3(4, 256), tb>>>(P, PSW, Y, B16a, NROWS, 128);
    tgemmF_k<false, false, false><<<gFw, 256, SMF>>>(S16, NROWS, B16a, NROWS, NROWS, 128,
                                                     T, B16b, nullptr, nullptr, nullptr,
                                                     nullptr, nullptr, nullptr);
    tgemmF_k<true, true, true><<<gFw, 256, SMF>>>(S16, NROWS, B16b, NROWS, NROWS, 128,
                                                  Z, nullptr, Y, T, h2, b2, Ahi, Alo);
    // ================= Layer 3 (W=64, no ReLU) =================
    convt_k<<<dim3(2, 4), tb>>>(W3, Whi, Wlo, 128, 64);
    tgemm3_k<64, 4><<<gW, 256, SM3N>>>(Ahi, Alo, 128, Whi, Wlo, 128, 128, P);
    combine_t16_k<2><<<dim3(2, 256), tb>>>(P, PSN, Y, B16a, NROWS, 64);
    tgemmF_k<false, false, false><<<gFn, 256, SMF>>>(S16, NROWS, B16a, NROWS, NROWS, 64,
                                                     T, B16b, nullptr, nullptr, nullptr,
                                                     nullptr, nullptr, nullptr);
    tgemmF_k<true, false, false><<<gFn, 256, SMF>>>(S16, NROWS, B16b, NROWS, NROWS, 64,
                                                    out, nullptr, Y, T, h3, b3,
                                                    nullptr, nullptr);
}

// round 15
// speedup vs baseline: 1.0369x; 1.0369x over previous
#include <cuda_runtime.h>
#include <cuda_bf16.h>
#include <cuda_fp16.h>
#include <cstdint>

#define NROWS 8192

// ---------------- scratch (__device__ globals; no allocation allowed) ----------
__device__ __align__(16) float g_Y[NROWS * 128];
__device__ __align__(16) float g_T[NROWS * 128];
__device__ __align__(16) float g_Z[NROWS * 128];
__device__ __align__(16) float g_P[2 * NROWS * 128];                  // split-K partials (X@W only)
__device__ __align__(16) __half g_S16[(size_t)NROWS * NROWS];         // fp16(S), 128 MB
__device__ __align__(16) __nv_bfloat16 g_Ahi[NROWS * 512];            // row acts, bf16 hi
__device__ __align__(16) __nv_bfloat16 g_Alo[NROWS * 512];            // row acts, bf16 lo
__device__ __align__(16) __half g_B16a[128 * NROWS];                  // transposed acts fp16 (ping)
__device__ __align__(16) __half g_B16b[128 * NROWS];                  // transposed acts fp16 (pong)
__device__ __align__(16) __nv_bfloat16 g_Whi[128 * 512];
__device__ __align__(16) __nv_bfloat16 g_Wlo[128 * 512];

__device__ __forceinline__ uint32_t smem_u32(const void* p) {
    uint32_t a;
    asm("{ .reg .u64 t; cvta.to.shared.u64 t, %1; cvt.u32.u64 %0, t; }" : "=r"(a) : "l"(p));
    return a;
}

#define LDSM_X4(r, addr)                                                        \
    asm volatile("ldmatrix.sync.aligned.m8n8.x4.shared.b16 {%0,%1,%2,%3}, [%4];"\
                 : "=r"((r)[0]), "=r"((r)[1]), "=r"((r)[2]), "=r"((r)[3])       \
                 : "r"(addr))

#define MMA_BF16(d, a, b)                                                       \
    asm volatile("mma.sync.aligned.m16n8k16.row.col.f32.bf16.bf16.f32 "         \
                 "{%0,%1,%2,%3}, {%4,%5,%6,%7}, {%8,%9}, {%0,%1,%2,%3};"        \
                 : "+f"((d)[0]), "+f"((d)[1]), "+f"((d)[2]), "+f"((d)[3])       \
                 : "r"((a)[0]), "r"((a)[1]), "r"((a)[2]), "r"((a)[3]),          \
                   "r"((b)[0]), "r"((b)[1]))

#define MMA_FP16(d, a, b)                                                       \
    asm volatile("mma.sync.aligned.m16n8k16.row.col.f32.f16.f16.f32 "           \
                 "{%0,%1,%2,%3}, {%4,%5,%6,%7}, {%8,%9}, {%0,%1,%2,%3};"        \
                 : "+f"((d)[0]), "+f"((d)[1]), "+f"((d)[2]), "+f"((d)[3])       \
                 : "r"((a)[0]), "r"((a)[1]), "r"((a)[2]), "r"((a)[3]),          \
                   "r"((b)[0]), "r"((b)[1]))

#define CP16(s, g)                                                              \
    asm volatile("cp.async.cg.shared.global [%0], [%1], 16;"                    \
                 :: "r"(s), "l"(g) : "memory")
#define CP_COMMIT() asm volatile("cp.async.commit_group;" ::: "memory")
#define CP_WAIT(n)  asm volatile("cp.async.wait_group %0;" :: "n"(n) : "memory")

__device__ __forceinline__ void split2(float a, float b, uint32_t& hi, uint32_t& lo) {
    __nv_bfloat162 H, L;
    H.x = __float2bfloat16(a);
    H.y = __float2bfloat16(b);
    L.x = __float2bfloat16(a - __bfloat162float(H.x));
    L.y = __float2bfloat16(b - __bfloat162float(H.y));
    hi = *reinterpret_cast<uint32_t*>(&H);
    lo = *reinterpret_cast<uint32_t*>(&L);
}

// ---------------- fp32 -> fp16 single convert (for S) --------------------------
__global__ void split_s16_k(const float* __restrict__ in, __half* __restrict__ o)
{
    size_t i = ((size_t)blockIdx.x * 256 + threadIdx.x) * 8;
    float4 v0 = *(const float4*)(in + i);
    float4 v1 = *(const float4*)(in + i + 4);
    __half2 h[4];
    h[0] = __floats2half2_rn(v0.x, v0.y);
    h[1] = __floats2half2_rn(v0.z, v0.w);
    h[2] = __floats2half2_rn(v1.x, v1.y);
    h[3] = __floats2half2_rn(v1.z, v1.w);
    *(uint4*)(o + i) = *reinterpret_cast<uint4*>(h);
}

// ---------------- row-major bf16 split (for X) ---------------------------------
__global__ void split_k(const float* __restrict__ in, __nv_bfloat16* __restrict__ ohi,
                        __nv_bfloat16* __restrict__ olo)
{
    size_t i = ((size_t)blockIdx.x * 256 + threadIdx.x) * 8;
    float4 v0 = *(const float4*)(in + i);
    float4 v1 = *(const float4*)(in + i + 4);
    uint4 H, L;
    split2(v0.x, v0.y, H.x, L.x);
    split2(v0.z, v0.w, H.y, L.y);
    split2(v1.x, v1.y, H.z, L.z);
    split2(v1.z, v1.w, H.w, L.w);
    *(uint4*)(ohi + i) = H;
    *(uint4*)(olo + i) = L;
}

// ---------------- transpose + bf16 split (for W) -------------------------------
__global__ void convt_k(const float* __restrict__ in, __nv_bfloat16* __restrict__ ohi,
                        __nv_bfloat16* __restrict__ olo, int R, int C)
{
    __shared__ float tile[32][33];
    const int bx = blockIdx.x * 32, by = blockIdx.y * 32;
    const int tx = threadIdx.x, ty = threadIdx.y;
#pragma unroll
    for (int i = 0; i < 32; i += 8)
        tile[ty + i][tx] = in[(size_t)(by + ty + i) * C + bx + tx];
    __syncthreads();
#pragma unroll
    for (int i = 0; i < 32; i += 8) {
        float v = tile[tx][ty + i];
        __nv_bfloat16 h = __float2bfloat16(v);
        size_t o = (size_t)(bx + ty + i) * R + by + tx;
        ohi[o] = h;
        olo[o] = __float2bfloat16(v - __bfloat162float(h));
    }
}

// ---------------- combine NP split-K partials + transpose fp16 convert ---------
// (used after X@W GEMMs only)
template <int NP>
__global__ void combine_t16_k(const float* __restrict__ P, size_t pstride,
                              float* __restrict__ Trm,
                              __half* __restrict__ o16, int R, int C)
{
    __shared__ float tile[32][33];
    const int bx = blockIdx.x * 32, by = blockIdx.y * 32;
    const int tx = threadIdx.x, ty = threadIdx.y;
#pragma unroll
    for (int i = 0; i < 32; i += 8) {
        size_t idx = (size_t)(by + ty + i) * C + bx + tx;
        float v = 0.f;
#pragma unroll
        for (int p = 0; p < NP; p++) v += P[idx + p * pstride];
        Trm[idx] = v;
        tile[ty + i][tx] = v;
    }
    __syncthreads();
#pragma unroll
    for (int i = 0; i < 32; i += 8) {
        float v = tile[tx][ty + i];
        o16[(size_t)(bx + ty + i) * R + by + tx] = __float2half(v);
    }
}

// ================== bf16 3-pass GEMM (X@W path), BM=128, 256 thr, split-K ======
template <int BN, int D>
__global__ void __launch_bounds__(256)
tgemm3_k(const __nv_bfloat16* __restrict__ Ahi, const __nv_bfloat16* __restrict__ Alo,
         int lda,
         const __nv_bfloat16* __restrict__ Bhi, const __nv_bfloat16* __restrict__ Blo,
         int ldb, int Ktot, float* __restrict__ C)
{
    extern __shared__ char sm[];
    constexpr int WN = BN / 4;
    constexpr int NT = WN / 8;
    constexpr int ASPL = 128 * 128;
    constexpr int BSPL = BN * 128;
    constexpr int STAGE = 2 * ASPL + 2 * BSPL;

    const int tid = threadIdx.x, wid = tid >> 5, lid = tid & 31;
    const int wm = wid & 1, wn = wid >> 1;
    const int m0 = blockIdx.x * 128;
    const int kslice = Ktot / gridDim.y;
    const int kbase = blockIdx.y * kslice;
    const int nk = kslice / 64;
    float* Cout = C + (size_t)blockIdx.y * (gridDim.x * 128) * BN;
    const uint32_t smb = smem_u32(sm);

    const int ldrow = tid >> 3, ldc = tid & 7;
    const int arl = lid & 15, ahf = lid >> 4;
    const int brl = (lid & 7) + ((lid >> 4) << 3);
    const int bhf = (lid >> 3) & 1;
    const int asw = arl & 7, bsw = lid & 7;

    float acc[2][2][NT][4];
#pragma unroll
    for (int s = 0; s < 2; s++)
#pragma unroll
        for (int mt = 0; mt < 2; mt++)
#pragma unroll
            for (int nt = 0; nt < NT; nt++)
#pragma unroll
                for (int j = 0; j < 4; j++) acc[s][mt][nt][j] = 0.f;

    auto issue = [&](int ch, int buf) {
        const uint32_t sb = smb + buf * STAGE;
        const int kg = kbase + ch * 64;
#pragma unroll
        for (int it = 0; it < 4; it++) {
            const int row = ldrow + 32 * it;
            const size_t go = (size_t)(m0 + row) * lda + kg + ldc * 8;
            const uint32_t so = sb + row * 128 + ((ldc ^ (row & 7)) << 4);
            CP16(so, (const void*)(Ahi + go));
            CP16(so + ASPL, (const void*)(Alo + go));
        }
#pragma unroll
        for (int it = 0; it < BN / 32; it++) {
            const int row = ldrow + 32 * it;
            const size_t go = (size_t)row * ldb + kg + ldc * 8;
            const uint32_t so = sb + 2 * ASPL + row * 128 + ((ldc ^ (row & 7)) << 4);
            CP16(so, (const void*)(Bhi + go));
            CP16(so + BSPL, (const void*)(Blo + go));
        }
    };

#pragma unroll
    for (int s = 0; s < D - 1; s++) {
        if (s < nk) issue(s, s);
        CP_COMMIT();
    }

    for (int i = 0; i < nk; i++) {
        CP_WAIT(D - 2);
        __syncthreads();
        if (i + D - 1 < nk) issue(i + D - 1, (i + D - 1) % D);
        CP_COMMIT();

        const uint32_t cab = smb + (i % D) * STAGE;
        const uint32_t cbb = cab + 2 * ASPL;

#pragma unroll
        for (int ks = 0; ks < 4; ks++) {
            uint32_t bH[NT][2], bL[NT][2];
#pragma unroll
            for (int p = 0; p < NT / 2; p++) {
                const uint32_t bo = (uint32_t)((wn * WN + p * 16 + brl) * 128)
                                  + (uint32_t)(((ks * 2 + bhf) ^ bsw) << 4);
                uint32_t t[4];
                LDSM_X4(t, cbb + bo);
                bH[2 * p][0] = t[0]; bH[2 * p][1] = t[1];
                bH[2 * p + 1][0] = t[2]; bH[2 * p + 1][1] = t[3];
                LDSM_X4(t, cbb + BSPL + bo);
                bL[2 * p][0] = t[0]; bL[2 * p][1] = t[1];
                bL[2 * p + 1][0] = t[2]; bL[2 * p + 1][1] = t[3];
            }
#pragma unroll
            for (int sub = 0; sub < 2; sub++) {
                uint32_t aH[2][4], aL[2][4];
#pragma unroll
                for (int mt = 0; mt < 2; mt++) {
                    const uint32_t ao = (uint32_t)((sub * 64 + wm * 32 + mt * 16 + arl) * 128)
                                      + (uint32_t)(((ks * 2 + ahf) ^ asw) << 4);
                    LDSM_X4(aH[mt], cab + ao);
                    LDSM_X4(aL[mt], cab + ASPL + ao);
                }
#pragma unroll
                for (int mt = 0; mt < 2; mt++)
#pragma unroll
                    for (int nt = 0; nt < NT; nt++) {
                        MMA_BF16(acc[sub][mt][nt], aH[mt], bH[nt]);
                        MMA_BF16(acc[sub][mt][nt], aH[mt], bL[nt]);
                        MMA_BF16(acc[sub][mt][nt], aL[mt], bH[nt]);
                    }
            }
        }
    }

#pragma unroll
    for (int sub = 0; sub < 2; sub++)
#pragma unroll
        for (int mt = 0; mt < 2; mt++)
#pragma unroll
            for (int half = 0; half < 2; half++) {
                const int row = m0 + sub * 64 + wm * 32 + mt * 16 + (lid >> 2) + half * 8;
#pragma unroll
                for (int nt = 0; nt < NT; nt++) {
                    const int col = wn * WN + nt * 8 + (lid & 3) * 2;
                    float2 v = make_float2(acc[sub][mt][nt][half * 2 + 0],
                                           acc[sub][mt][nt][half * 2 + 1]);
                    *(float2*)(Cout + (size_t)row * BN + col) = v;
                }
            }
}

// ====== fp16 1-pass S-GEMM, fused epilogue, BN = FULL WIDTH ====================
// BM=64, 256 thr (8 warps, 2m x 4n, warp tile 32 x BN/4), grid = M/64, no split-K.
// S is read exactly once. B16 (2 MB) stays L2-resident.
// EPI=false: C = acc AND B16out[col][row] = fp16(acc)  (transposed)
// EPI=true : v = h0*Y + h1*T + h2*acc + bias; RELU?; C = v; WSPLIT: zhi/zlo bf16 split
template <int BN, int D, bool EPI, bool RELU, bool WSPLIT>
__global__ void __launch_bounds__(256)
tgemmF_k(const __half* __restrict__ A16, int lda,
         const __half* __restrict__ B16, int ldb, int Ktot,
         float* __restrict__ C, __half* __restrict__ B16out,
         const float* __restrict__ Ybuf, const float* __restrict__ Tbuf,
         const float* __restrict__ hv, const float* __restrict__ bias,
         __nv_bfloat16* __restrict__ zhi, __nv_bfloat16* __restrict__ zlo)
{
    extern __shared__ char sm[];
    constexpr int WN = BN / 4;          // 32 (wide) or 16 (narrow)
    constexpr int NT = WN / 8;          // 4 or 2
    constexpr int ASPL = 64 * 128;      // 8 KB
    constexpr int BSPL = BN * 128;      // 16 KB or 8 KB
    constexpr int STAGE = ASPL + BSPL;

    const int tid = threadIdx.x, wid = tid >> 5, lid = tid & 31;
    const int wm = wid & 1, wn = wid >> 1;      // 2 m-warps x 4 n-warps
    const int m0 = blockIdx.x * 64;
    const int nk = Ktot / 64;
    const uint32_t smb = smem_u32(sm);

    const int ldrow = tid >> 3, ldc = tid & 7;  // 0..31 rows per iter
    const int arl = lid & 15, ahf = lid >> 4;
    const int brl = (lid & 7) + ((lid >> 4) << 3);
    const int bhf = (lid >> 3) & 1;
    const int asw = arl & 7, bsw = lid & 7;

    float acc[2][NT][4];                // warp tile 32 x WN
#pragma unroll
    for (int mt = 0; mt < 2; mt++)
#pragma unroll
        for (int nt = 0; nt < NT; nt++)
#pragma unroll
            for (int j = 0; j < 4; j++) acc[mt][nt][j] = 0.f;

    auto issue = [&](int ch, int buf) {
        const uint32_t sb = smb + buf * STAGE;
        const int kg = ch * 64;
#pragma unroll
        for (int it = 0; it < 2; it++) {               // A: 64 rows
            const int row = ldrow + 32 * it;
            const size_t go = (size_t)(m0 + row) * lda + kg + ldc * 8;
            const uint32_t sw = (uint32_t)(row * 128 + ((ldc ^ (row & 7)) << 4));
            CP16(sb + sw, (const void*)(A16 + go));
        }
#pragma unroll
        for (int it = 0; it < BN / 32; it++) {         // B: BN rows
            const int row = ldrow + 32 * it;
            const size_t go = (size_t)row * ldb + kg + ldc * 8;
            const uint32_t sw = (uint32_t)(row * 128 + ((ldc ^ (row & 7)) << 4));
            CP16(sb + ASPL + sw, (const void*)(B16 + go));
        }
    };

#pragma unroll
    for (int s = 0; s < D - 1; s++) {
        if (s < nk) issue(s, s);
        CP_COMMIT();
    }

    for (int i = 0; i < nk; i++) {
        CP_WAIT(D - 2);
        __syncthreads();
        if (i + D - 1 < nk) issue(i + D - 1, (i + D - 1) % D);
        CP_COMMIT();

        const uint32_t cab = smb + (i % D) * STAGE;
        const uint32_t cbb = cab + ASPL;

#pragma unroll
        for (int ks = 0; ks < 4; ks++) {
            uint32_t bF[NT][2];
#pragma unroll
            for (int p = 0; p < NT / 2; p++) {
                const uint32_t bo = (uint32_t)((wn * WN + p * 16 + brl) * 128)
                                  + (uint32_t)(((ks * 2 + bhf) ^ bsw) << 4);
                uint32_t t[4];
                LDSM_X4(t, cbb + bo);
                bF[2 * p][0] = t[0]; bF[2 * p][1] = t[1];
                bF[2 * p + 1][0] = t[2]; bF[2 * p + 1][1] = t[3];
            }
            uint32_t aF[2][4];
#pragma unroll
            for (int mt = 0; mt < 2; mt++) {
                const uint32_t ao = (uint32_t)((wm * 32 + mt * 16 + arl) * 128)
                                  + (uint32_t)(((ks * 2 + ahf) ^ asw) << 4);
                LDSM_X4(aF[mt], cab + ao);
            }
#pragma unroll
            for (int mt = 0; mt < 2; mt++)
#pragma unroll
                for (int nt = 0; nt < NT; nt++)
                    MMA_FP16(acc[mt][nt], aF[mt], bF[nt]);
        }
    }

    // ---- fused epilogue ----
    float c0 = 0.f, c1 = 0.f, c2 = 0.f;
    if (EPI) { c0 = hv[0]; c1 = hv[1]; c2 = hv[2]; }
#pragma unroll
    for (int mt = 0; mt < 2; mt++) {
#pragma unroll
        for (int half = 0; half < 2; half++) {
            const int row = m0 + wm * 32 + mt * 16 + (lid >> 2) + half * 8;
#pragma unroll
            for (int nt = 0; nt < NT; nt++) {
                const int col = wn * WN + nt * 8 + (lid & 3) * 2;
                float2 v = make_float2(acc[mt][nt][half * 2 + 0],
                                       acc[mt][nt][half * 2 + 1]);
                const size_t ro = (size_t)row * BN + col;
                if (EPI) {
                    const float2 y = *(const float2*)(Ybuf + ro);
                    const float2 t = *(const float2*)(Tbuf + ro);
                    const float2 bb = *(const float2*)(bias + col);
                    v.x = c0 * y.x + c1 * t.x + c2 * v.x + bb.x;
                    v.y = c0 * y.y + c1 * t.y + c2 * v.y + bb.y;
                    if (RELU) { v.x = fmaxf(v.x, 0.f); v.y = fmaxf(v.y, 0.f); }
                    *(float2*)(C + ro) = v;
                    if (WSPLIT) {
                        uint32_t H, L;
                        split2(v.x, v.y, H, L);
                        *(uint32_t*)(zhi + ro) = H;
                        *(uint32_t*)(zlo + ro) = L;
                    }
                } else {
                    *(float2*)(C + ro) = v;
                    B16out[(size_t)col * NROWS + row] = __float2half(v.x);
                    B16out[(size_t)(col + 1) * NROWS + row] = __float2half(v.y);
                }
            }
        }
    }
}

// -------------------------------------------------------------------------------
extern "C" void kernel_launch(void* const* d_in, const int* in_sizes, int n_in,
                              void* d_out, int out_size)
{
    (void)in_sizes; (void)n_in; (void)out_size;
    const float* S  = (const float*)d_in[0];
    const float* X  = (const float*)d_in[1];
    const float* W1 = (const float*)d_in[2];
    const float* h1 = (const float*)d_in[3];
    const float* b1 = (const float*)d_in[4];
    const float* W2 = (const float*)d_in[5];
    const float* h2 = (const float*)d_in[6];
    const float* b2 = (const float*)d_in[7];
    const float* W3 = (const float*)d_in[8];
    const float* h3 = (const float*)d_in[9];
    const float* b3 = (const float*)d_in[10];
    float* out = (float*)d_out;

    float *Y, *T, *Z, *P;
    __half *S16, *B16a, *B16b;
    __nv_bfloat16 *Ahi, *Alo, *Whi, *Wlo;
    cudaGetSymbolAddress((void**)&Y, g_Y);
    cudaGetSymbolAddress((void**)&T, g_T);
    cudaGetSymbolAddress((void**)&Z, g_Z);
    cudaGetSymbolAddress((void**)&P, g_P);
    cudaGetSymbolAddress((void**)&S16, g_S16);
    cudaGetSymbolAddress((void**)&B16a, g_B16a);
    cudaGetSymbolAddress((void**)&B16b, g_B16b);
    cudaGetSymbolAddress((void**)&Ahi, g_Ahi);
    cudaGetSymbolAddress((void**)&Alo, g_Alo);
    cudaGetSymbolAddress((void**)&Whi, g_Whi);
    cudaGetSymbolAddress((void**)&Wlo, g_Wlo);

    const size_t PSW = (size_t)NROWS * 128;   // partial stride, BN=128 (X@W)
    const size_t PSN = (size_t)NROWS * 64;    // partial stride, BN=64  (X@W3)

    const int SM3W = 3 * (2 * 16384 + 2 * 16384);  // 196608: bf16 3-pass, BN=128, D=3
    const int SM3N = 4 * (2 * 16384 + 2 * 8192);   // 196608: bf16 3-pass, BN=64,  D=4
    const int SMFW = 4 * (8192 + 16384);           //  98304: fused S-GEMM, BN=128, D=4
    const int SMFN = 6 * (8192 + 8192);            //  98304: fused S-GEMM, BN=64,  D=6
    cudaFuncSetAttribute(tgemm3_k<128, 3>, cudaFuncAttributeMaxDynamicSharedMemorySize, SM3W);
    cudaFuncSetAttribute(tgemm3_k<64, 4>,  cudaFuncAttributeMaxDynamicSharedMemorySize, SM3N);
    cudaFuncSetAttribute(tgemmF_k<128, 4, false, false, false>, cudaFuncAttributeMaxDynamicSharedMemorySize, SMFW);
    cudaFuncSetAttribute(tgemmF_k<128, 4, true,  true,  true >, cudaFuncAttributeMaxDynamicSharedMemorySize, SMFW);
    cudaFuncSetAttribute(tgemmF_k<64,  6, false, false, false>, cudaFuncAttributeMaxDynamicSharedMemorySize, SMFN);
    cudaFuncSetAttribute(tgemmF_k<64,  6, true,  false, false>, cudaFuncAttributeMaxDynamicSharedMemorySize, SMFN);

    const dim3 tb(32, 8);
    const dim3 gW(NROWS / 128, 2);        // X@W: BM=128, split-K2 (128 CTAs)
    const dim3 gF(NROWS / 64);            // fused S-GEMM: 128 CTAs, full width

    // one-time converts
    split_s16_k<<<(size_t)NROWS * NROWS / 2048, 256>>>(S, S16);
    split_k<<<NROWS * 512 / 2048, 256>>>(X, Ahi, Alo);

    // ================= Layer 1 =================
    convt_k<<<dim3(4, 16), tb>>>(W1, Whi, Wlo, 512, 128);
    tgemm3_k<128, 3><<<gW, 256, SM3W>>>(Ahi, Alo, 512, Whi, Wlo, 512, 512, P);
    combine_t16_k<2><<<dim3(4, 256), tb>>>(P, PSW, Y, B16a, NROWS, 128);
    tgemmF_k<128, 4, false, false, false><<<gF, 256, SMFW>>>(S16, NROWS, B16a, NROWS, NROWS,
                                                             T, B16b, nullptr, nullptr,
                                                             nullptr, nullptr, nullptr, nullptr);
    tgemmF_k<128, 4, true, true, true><<<gF, 256, SMFW>>>(S16, NROWS, B16b, NROWS, NROWS,
                                                          Z, nullptr, Y, T, h1, b1, Ahi, Alo);
    // ================= Layer 2 =================
    convt_k<<<dim3(4, 4), tb>>>(W2, Whi, Wlo, 128, 128);
    tgemm3_k<128, 3><<<gW, 256, SM3W>>>(Ahi, Alo, 128, Whi, Wlo, 128, 128, P);
    combine_t16_k<2><<<dim3(4, 256), tb>>>(P, PSW, Y, B16a, NROWS, 128);
    tgemmF_k<128, 4, false, false, false><<<gF, 256, SMFW>>>(S16, NROWS, B16a, NROWS, NROWS,
                                                             T, B16b, nullptr, nullptr,
                                                             nullptr, nullptr, nullptr, nullptr);
    tgemmF_k<128, 4, true, true, true><<<gF, 256, SMFW>>>(S16, NROWS, B16b, NROWS, NROWS,
                                                          Z, nullptr, Y, T, h2, b2, Ahi, Alo);
    // ================= Layer 3 (W=64, no ReLU) =================
    convt_k<<<dim3(2, 4), tb>>>(W3, Whi, Wlo, 128, 64);
    tgemm3_k<64, 4><<<gW, 256, SM3N>>>(Ahi, Alo, 128, Whi, Wlo, 128, 128, P);
    combine_t16_k<2><<<dim3(2, 256), tb>>>(P, PSN, Y, B16a, NROWS, 64);
    tgemmF_k<64, 6, false, false, false><<<gF, 256, SMFN>>>(S16, NROWS, B16a, NROWS, NROWS,
                                                            T, B16b, nullptr, nullptr,
                                                            nullptr, nullptr, nullptr, nullptr);
    tgemmF_k<64, 6, true, false, false><<<gF, 256, SMFN>>>(S16, NROWS, B16b, NROWS, NROWS,
                                                           out, nullptr, Y, T, h3, b3,
                                                           nullptr, nullptr);
}

// round 16
// speedup vs baseline: 1.2425x; 1.1982x over previous
#include <cuda_runtime.h>
#include <cuda_bf16.h>
#include <cuda_fp16.h>
#include <cstdint>

#define NROWS 8192

// ---------------- scratch (__device__ globals; no allocation allowed) ----------
__device__ __align__(16) float g_Y[NROWS * 128];
__device__ __align__(16) float g_T[NROWS * 128];
__device__ __align__(16) float g_Z[NROWS * 128];
__device__ __align__(16) float g_P[4 * NROWS * 128];                  // split-K partials (16 MB)
__device__ __align__(16) __half g_S16[(size_t)NROWS * NROWS];         // fp16(S), 128 MB
__device__ __align__(16) __nv_bfloat16 g_Ahi[NROWS * 512];            // row acts, bf16 hi
__device__ __align__(16) __nv_bfloat16 g_Alo[NROWS * 512];            // row acts, bf16 lo
__device__ __align__(16) __half g_B16[128 * NROWS];                   // transposed acts fp16
__device__ __align__(16) __nv_bfloat16 g_Whi[128 * 512];
__device__ __align__(16) __nv_bfloat16 g_Wlo[128 * 512];

__device__ __forceinline__ uint32_t smem_u32(const void* p) {
    uint32_t a;
    asm("{ .reg .u64 t; cvta.to.shared.u64 t, %1; cvt.u32.u64 %0, t; }" : "=r"(a) : "l"(p));
    return a;
}

#define LDSM_X4(r, addr)                                                        \
    asm volatile("ldmatrix.sync.aligned.m8n8.x4.shared.b16 {%0,%1,%2,%3}, [%4];"\
                 : "=r"((r)[0]), "=r"((r)[1]), "=r"((r)[2]), "=r"((r)[3])       \
                 : "r"(addr))

#define MMA_BF16(d, a, b)                                                       \
    asm volatile("mma.sync.aligned.m16n8k16.row.col.f32.bf16.bf16.f32 "         \
                 "{%0,%1,%2,%3}, {%4,%5,%6,%7}, {%8,%9}, {%0,%1,%2,%3};"        \
                 : "+f"((d)[0]), "+f"((d)[1]), "+f"((d)[2]), "+f"((d)[3])       \
                 : "r"((a)[0]), "r"((a)[1]), "r"((a)[2]), "r"((a)[3]),          \
                   "r"((b)[0]), "r"((b)[1]))

#define MMA_FP16(d, a, b)                                                       \
    asm volatile("mma.sync.aligned.m16n8k16.row.col.f32.f16.f16.f32 "           \
                 "{%0,%1,%2,%3}, {%4,%5,%6,%7}, {%8,%9}, {%0,%1,%2,%3};"        \
                 : "+f"((d)[0]), "+f"((d)[1]), "+f"((d)[2]), "+f"((d)[3])       \
                 : "r"((a)[0]), "r"((a)[1]), "r"((a)[2]), "r"((a)[3]),          \
                   "r"((b)[0]), "r"((b)[1]))

#define CP16(s, g)                                                              \
    asm volatile("cp.async.cg.shared.global [%0], [%1], 16;"                    \
                 :: "r"(s), "l"(g) : "memory")
#define CP_COMMIT() asm volatile("cp.async.commit_group;" ::: "memory")
#define CP_WAIT(n)  asm volatile("cp.async.wait_group %0;" :: "n"(n) : "memory")

__device__ __forceinline__ void split2(float a, float b, uint32_t& hi, uint32_t& lo) {
    __nv_bfloat162 H, L;
    H.x = __float2bfloat16(a);
    H.y = __float2bfloat16(b);
    L.x = __float2bfloat16(a - __bfloat162float(H.x));
    L.y = __float2bfloat16(b - __bfloat162float(H.y));
    hi = *reinterpret_cast<uint32_t*>(&H);
    lo = *reinterpret_cast<uint32_t*>(&L);
}

// ---------------- fp32 -> fp16 single convert (for S) --------------------------
__global__ void split_s16_k(const float* __restrict__ in, __half* __restrict__ o)
{
    size_t i = ((size_t)blockIdx.x * 256 + threadIdx.x) * 8;
    float4 v0 = *(const float4*)(in + i);
    float4 v1 = *(const float4*)(in + i + 4);
    __half2 h[4];
    h[0] = __floats2half2_rn(v0.x, v0.y);
    h[1] = __floats2half2_rn(v0.z, v0.w);
    h[2] = __floats2half2_rn(v1.x, v1.y);
    h[3] = __floats2half2_rn(v1.z, v1.w);
    *(uint4*)(o + i) = *reinterpret_cast<uint4*>(h);
}

// ---------------- row-major bf16 split (for X) ---------------------------------
__global__ void split_k(const float* __restrict__ in, __nv_bfloat16* __restrict__ ohi,
                        __nv_bfloat16* __restrict__ olo)
{
    size_t i = ((size_t)blockIdx.x * 256 + threadIdx.x) * 8;
    float4 v0 = *(const float4*)(in + i);
    float4 v1 = *(const float4*)(in + i + 4);
    uint4 H, L;
    split2(v0.x, v0.y, H.x, L.x);
    split2(v0.z, v0.w, H.y, L.y);
    split2(v1.x, v1.y, H.z, L.z);
    split2(v1.z, v1.w, H.w, L.w);
    *(uint4*)(ohi + i) = H;
    *(uint4*)(olo + i) = L;
}

// ---------------- transpose + bf16 split (for W) -------------------------------
__global__ void convt_k(const float* __restrict__ in, __nv_bfloat16* __restrict__ ohi,
                        __nv_bfloat16* __restrict__ olo, int R, int C)
{
    __shared__ float tile[32][33];
    const int bx = blockIdx.x * 32, by = blockIdx.y * 32;
    const int tx = threadIdx.x, ty = threadIdx.y;
#pragma unroll
    for (int i = 0; i < 32; i += 8)
        tile[ty + i][tx] = in[(size_t)(by + ty + i) * C + bx + tx];
    __syncthreads();
#pragma unroll
    for (int i = 0; i < 32; i += 8) {
        float v = tile[tx][ty + i];
        __nv_bfloat16 h = __float2bfloat16(v);
        size_t o = (size_t)(bx + ty + i) * R + by + tx;
        ohi[o] = h;
        olo[o] = __float2bfloat16(v - __bfloat162float(h));
    }
}

// ---------------- combine NP split-K partials + transpose fp16 convert ---------
template <int NP>
__global__ void combine_t16_k(const float* __restrict__ P, size_t pstride,
                              float* __restrict__ Trm,
                              __half* __restrict__ o16, int R, int C)
{
    __shared__ float tile[32][33];
    const int bx = blockIdx.x * 32, by = blockIdx.y * 32;
    const int tx = threadIdx.x, ty = threadIdx.y;
#pragma unroll
    for (int i = 0; i < 32; i += 8) {
        size_t idx = (size_t)(by + ty + i) * C + bx + tx;
        float v = 0.f;
#pragma unroll
        for (int p = 0; p < NP; p++) v += P[idx + p * pstride];
        Trm[idx] = v;
        tile[ty + i][tx] = v;
    }
    __syncthreads();
#pragma unroll
    for (int i = 0; i < 32; i += 8) {
        float v = tile[tx][ty + i];
        o16[(size_t)(bx + ty + i) * R + by + tx] = __float2half(v);
    }
}

// ---------------- combine NP partials + poly epilogue (+optional bf16 split) ---
template <int NP, bool RELU, bool WSPLIT>
__global__ void combine_epi_k(const float* __restrict__ P, size_t pstride,
                              const float* __restrict__ Y, const float* __restrict__ T,
                              const float* __restrict__ hv, const float* __restrict__ bias,
                              float* __restrict__ Z,
                              __nv_bfloat16* __restrict__ zhi, __nv_bfloat16* __restrict__ zlo,
                              int nmask)
{
    const size_t i = ((size_t)blockIdx.x * 256 + threadIdx.x) * 4;
    const float c0 = hv[0], c1 = hv[1], c2 = hv[2];
    float4 s = *(const float4*)(P + i);
#pragma unroll
    for (int p = 1; p < NP; p++) {
        const float4 q = *(const float4*)(P + i + p * pstride);
        s.x += q.x; s.y += q.y; s.z += q.z; s.w += q.w;
    }
    const float4 y  = *(const float4*)(Y + i);
    const float4 t  = *(const float4*)(T + i);
    const float4 bb = *(const float4*)(bias + (i & nmask));
    float4 v;
    v.x = c0 * y.x + c1 * t.x + c2 * s.x + bb.x;
    v.y = c0 * y.y + c1 * t.y + c2 * s.y + bb.y;
    v.z = c0 * y.z + c1 * t.z + c2 * s.z + bb.z;
    v.w = c0 * y.w + c1 * t.w + c2 * s.w + bb.w;
    if (RELU) {
        v.x = fmaxf(v.x, 0.f); v.y = fmaxf(v.y, 0.f);
        v.z = fmaxf(v.z, 0.f); v.w = fmaxf(v.w, 0.f);
    }
    *(float4*)(Z + i) = v;
    if (WSPLIT) {
        uint2 H, L;
        split2(v.x, v.y, H.x, L.x);
        split2(v.z, v.w, H.y, L.y);
        *(uint2*)(zhi + i) = H;
        *(uint2*)(zlo + i) = L;
    }
}

// ================== bf16 3-pass GEMM (X@W path), BM=128, 256 thr, split-K ======
template <int BN, int D>
__global__ void __launch_bounds__(256)
tgemm3_k(const __nv_bfloat16* __restrict__ Ahi, const __nv_bfloat16* __restrict__ Alo,
         int lda,
         const __nv_bfloat16* __restrict__ Bhi, const __nv_bfloat16* __restrict__ Blo,
         int ldb, int Ktot, float* __restrict__ C)
{
    extern __shared__ char sm[];
    constexpr int WN = BN / 4;
    constexpr int NT = WN / 8;
    constexpr int ASPL = 128 * 128;
    constexpr int BSPL = BN * 128;
    constexpr int STAGE = 2 * ASPL + 2 * BSPL;

    const int tid = threadIdx.x, wid = tid >> 5, lid = tid & 31;
    const int wm = wid & 1, wn = wid >> 1;
    const int m0 = blockIdx.x * 128;
    const int kslice = Ktot / gridDim.y;
    const int kbase = blockIdx.y * kslice;
    const int nk = kslice / 64;
    float* Cout = C + (size_t)blockIdx.y * (gridDim.x * 128) * BN;
    const uint32_t smb = smem_u32(sm);

    const int ldrow = tid >> 3, ldc = tid & 7;
    const int arl = lid & 15, ahf = lid >> 4;
    const int brl = (lid & 7) + ((lid >> 4) << 3);
    const int bhf = (lid >> 3) & 1;
    const int asw = arl & 7, bsw = lid & 7;

    float acc[2][2][NT][4];
#pragma unroll
    for (int s = 0; s < 2; s++)
#pragma unroll
        for (int mt = 0; mt < 2; mt++)
#pragma unroll
            for (int nt = 0; nt < NT; nt++)
#pragma unroll
                for (int j = 0; j < 4; j++) acc[s][mt][nt][j] = 0.f;

    auto issue = [&](int ch, int buf) {
        const uint32_t sb = smb + buf * STAGE;
        const int kg = kbase + ch * 64;
#pragma unroll
        for (int it = 0; it < 4; it++) {
            const int row = ldrow + 32 * it;
            const size_t go = (size_t)(m0 + row) * lda + kg + ldc * 8;
            const uint32_t so = sb + row * 128 + ((ldc ^ (row & 7)) << 4);
            CP16(so, (const void*)(Ahi + go));
            CP16(so + ASPL, (const void*)(Alo + go));
        }
#pragma unroll
        for (int it = 0; it < BN / 32; it++) {
            const int row = ldrow + 32 * it;
            const size_t go = (size_t)row * ldb + kg + ldc * 8;
            const uint32_t so = sb + 2 * ASPL + row * 128 + ((ldc ^ (row & 7)) << 4);
            CP16(so, (const void*)(Bhi + go));
            CP16(so + BSPL, (const void*)(Blo + go));
        }
    };

#pragma unroll
    for (int s = 0; s < D - 1; s++) {
        if (s < nk) issue(s, s);
        CP_COMMIT();
    }

    for (int i = 0; i < nk; i++) {
        CP_WAIT(D - 2);
        __syncthreads();
        if (i + D - 1 < nk) issue(i + D - 1, (i + D - 1) % D);
        CP_COMMIT();

        const uint32_t cab = smb + (i % D) * STAGE;
        const uint32_t cbb = cab + 2 * ASPL;

#pragma unroll
        for (int ks = 0; ks < 4; ks++) {
            uint32_t bH[NT][2], bL[NT][2];
#pragma unroll
            for (int p = 0; p < NT / 2; p++) {
                const uint32_t bo = (uint32_t)((wn * WN + p * 16 + brl) * 128)
                                  + (uint32_t)(((ks * 2 + bhf) ^ bsw) << 4);
                uint32_t t[4];
                LDSM_X4(t, cbb + bo);
                bH[2 * p][0] = t[0]; bH[2 * p][1] = t[1];
                bH[2 * p + 1][0] = t[2]; bH[2 * p + 1][1] = t[3];
                LDSM_X4(t, cbb + BSPL + bo);
                bL[2 * p][0] = t[0]; bL[2 * p][1] = t[1];
                bL[2 * p + 1][0] = t[2]; bL[2 * p + 1][1] = t[3];
            }
#pragma unroll
            for (int sub = 0; sub < 2; sub++) {
                uint32_t aH[2][4], aL[2][4];
#pragma unroll
                for (int mt = 0; mt < 2; mt++) {
                    const uint32_t ao = (uint32_t)((sub * 64 + wm * 32 + mt * 16 + arl) * 128)
                                      + (uint32_t)(((ks * 2 + ahf) ^ asw) << 4);
                    LDSM_X4(aH[mt], cab + ao);
                    LDSM_X4(aL[mt], cab + ASPL + ao);
                }
#pragma unroll
                for (int mt = 0; mt < 2; mt++)
#pragma unroll
                    for (int nt = 0; nt < NT; nt++) {
                        MMA_BF16(acc[sub][mt][nt], aH[mt], bH[nt]);
                        MMA_BF16(acc[sub][mt][nt], aH[mt], bL[nt]);
                        MMA_BF16(acc[sub][mt][nt], aL[mt], bH[nt]);
                    }
            }
        }
    }

#pragma unroll
    for (int sub = 0; sub < 2; sub++)
#pragma unroll
        for (int mt = 0; mt < 2; mt++)
#pragma unroll
            for (int half = 0; half < 2; half++) {
                const int row = m0 + sub * 64 + wm * 32 + mt * 16 + (lid >> 2) + half * 8;
#pragma unroll
                for (int nt = 0; nt < NT; nt++) {
                    const int col = wn * WN + nt * 8 + (lid & 3) * 2;
                    float2 v = make_float2(acc[sub][mt][nt][half * 2 + 0],
                                           acc[sub][mt][nt][half * 2 + 1]);
                    *(float2*)(Cout + (size_t)row * BN + col) = v;
                }
            }
}

// ================== fp16 1-pass S-GEMM: BM=256, 512 thr (16 warps, 4m x 4n) ====
template <int BN, int D>
__global__ void __launch_bounds__(512)
tgemmS_k(const __half* __restrict__ A16, int lda,
         const __half* __restrict__ B16, int ldb, int Ktot, float* __restrict__ C)
{
    extern __shared__ char sm[];
    constexpr int WN = BN / 4;          // warp n extent (32 or 16)
    constexpr int NT = WN / 8;          // 4 or 2
    constexpr int ASPL = 256 * 128;     // A: 256 rows x 128B fp16
    constexpr int BSPL = BN * 128;      // B: BN rows x 128B fp16
    constexpr int STAGE = ASPL + BSPL;

    const int tid = threadIdx.x, wid = tid >> 5, lid = tid & 31;
    const int wm = wid & 3, wn = wid >> 2;     // 4 m-warps x 4 n-warps
    const int m0 = blockIdx.x * 256;
    const int kslice = Ktot / gridDim.y;
    const int kbase = blockIdx.y * kslice;
    const int nk = kslice / 64;
    float* Cout = C + (size_t)blockIdx.y * (gridDim.x * 256) * BN;
    const uint32_t smb = smem_u32(sm);

    const int ldrow = tid >> 3, ldc = tid & 7;  // ldrow in 0..63
    const int arl = lid & 15, ahf = lid >> 4;
    const int brl = (lid & 7) + ((lid >> 4) << 3);
    const int bhf = (lid >> 3) & 1;
    const int asw = arl & 7, bsw = lid & 7;

    float acc[4][NT][4];                // warp tile 64 x WN
#pragma unroll
    for (int mt = 0; mt < 4; mt++)
#pragma unroll
        for (int nt = 0; nt < NT; nt++)
#pragma unroll
            for (int j = 0; j < 4; j++) acc[mt][nt][j] = 0.f;

    auto issue = [&](int ch, int buf) {
        const uint32_t sb = smb + buf * STAGE;
        const int kg = kbase + ch * 64;
#pragma unroll
        for (int it = 0; it < 4; it++) {               // A: 256 rows fp16
            const int row = ldrow + 64 * it;
            const size_t go = (size_t)(m0 + row) * lda + kg + ldc * 8;
            const uint32_t so = sb + row * 128 + ((ldc ^ (row & 7)) << 4);
            CP16(so, (const void*)(A16 + go));
        }
#pragma unroll
        for (int it = 0; it < BN / 64; it++) {         // B: single fp16
            const int row = ldrow + 64 * it;
            const size_t go = (size_t)row * ldb + kg + ldc * 8;
            const uint32_t so = sb + ASPL + row * 128 + ((ldc ^ (row & 7)) << 4);
            CP16(so, (const void*)(B16 + go));
        }
    };

#pragma unroll
    for (int s = 0; s < D - 1; s++) {
        if (s < nk) issue(s, s);
        CP_COMMIT();
    }

    for (int i = 0; i < nk; i++) {
        CP_WAIT(D - 2);
        __syncthreads();
        if (i + D - 1 < nk) issue(i + D - 1, (i + D - 1) % D);
        CP_COMMIT();

        const uint32_t cab = smb + (i % D) * STAGE;
        const uint32_t cbb = cab + ASPL;

#pragma unroll
        for (int ks = 0; ks < 4; ks++) {
            uint32_t bH[NT][2];
#pragma unroll
            for (int p = 0; p < NT / 2; p++) {
                const uint32_t bo = (uint32_t)((wn * WN + p * 16 + brl) * 128)
                                  + (uint32_t)(((ks * 2 + bhf) ^ bsw) << 4);
                uint32_t t[4];
                LDSM_X4(t, cbb + bo);
                bH[2 * p][0] = t[0]; bH[2 * p][1] = t[1];
                bH[2 * p + 1][0] = t[2]; bH[2 * p + 1][1] = t[3];
            }
            uint32_t aF[4][4];
#pragma unroll
            for (int mt = 0; mt < 4; mt++) {
                const uint32_t ao = (uint32_t)((wm * 64 + mt * 16 + arl) * 128)
                                  + (uint32_t)(((ks * 2 + ahf) ^ asw) << 4);
                LDSM_X4(aF[mt], cab + ao);
            }
#pragma unroll
            for (int mt = 0; mt < 4; mt++)
#pragma unroll
                for (int nt = 0; nt < NT; nt++)
                    MMA_FP16(acc[mt][nt], aF[mt], bH[nt]);
        }
    }

    // ---- write partial tile ----
#pragma unroll
    for (int mt = 0; mt < 4; mt++)
#pragma unroll
        for (int half = 0; half < 2; half++) {
            const int row = m0 + wm * 64 + mt * 16 + (lid >> 2) + half * 8;
#pragma unroll
            for (int nt = 0; nt < NT; nt++) {
                const int col = wn * WN + nt * 8 + (lid & 3) * 2;
                float2 v = make_float2(acc[mt][nt][half * 2 + 0],
                                       acc[mt][nt][half * 2 + 1]);
                *(float2*)(Cout + (size_t)row * BN + col) = v;
            }
        }
}

// -------------------------------------------------------------------------------
extern "C" void kernel_launch(void* const* d_in, const int* in_sizes, int n_in,
                              void* d_out, int out_size)
{
    (void)in_sizes; (void)n_in; (void)out_size;
    const float* S  = (const float*)d_in[0];
    const float* X  = (const float*)d_in[1];
    const float* W1 = (const float*)d_in[2];
    const float* h1 = (const float*)d_in[3];
    const float* b1 = (const float*)d_in[4];
    const float* W2 = (const float*)d_in[5];
    const float* h2 = (const float*)d_in[6];
    const float* b2 = (const float*)d_in[7];
    const float* W3 = (const float*)d_in[8];
    const float* h3 = (const float*)d_in[9];
    const float* b3 = (const float*)d_in[10];
    float* out = (float*)d_out;

    float *Y, *T, *Z, *P;
    __half *S16, *B16;
    __nv_bfloat16 *Ahi, *Alo, *Whi, *Wlo;
    cudaGetSymbolAddress((void**)&Y, g_Y);
    cudaGetSymbolAddress((void**)&T, g_T);
    cudaGetSymbolAddress((void**)&Z, g_Z);
    cudaGetSymbolAddress((void**)&P, g_P);
    cudaGetSymbolAddress((void**)&S16, g_S16);
    cudaGetSymbolAddress((void**)&B16, g_B16);
    cudaGetSymbolAddress((void**)&Ahi, g_Ahi);
    cudaGetSymbolAddress((void**)&Alo, g_Alo);
    cudaGetSymbolAddress((void**)&Whi, g_Whi);
    cudaGetSymbolAddress((void**)&Wlo, g_Wlo);

    const size_t PSW = (size_t)NROWS * 128;   // partial stride, BN=128
    const size_t PSN = (size_t)NROWS * 64;    // partial stride, BN=64

    const int SM3W = 3 * (2 * 16384 + 2 * 16384);  // 196608: bf16 3-pass, BN=128, D=3
    const int SM3N = 4 * (2 * 16384 + 2 * 8192);   // 196608: bf16 3-pass, BN=64,  D=4
    const int SMSW = 4 * (32768 + 16384);          // 196608: fp16 S-GEMM, BN=128, D=4
    const int SMSN = 4 * (32768 + 8192);           // 163840: fp16 S-GEMM, BN=64,  D=4
    cudaFuncSetAttribute(tgemm3_k<128, 3>, cudaFuncAttributeMaxDynamicSharedMemorySize, SM3W);
    cudaFuncSetAttribute(tgemm3_k<64, 4>,  cudaFuncAttributeMaxDynamicSharedMemorySize, SM3N);
    cudaFuncSetAttribute(tgemmS_k<128, 4>, cudaFuncAttributeMaxDynamicSharedMemorySize, SMSW);
    cudaFuncSetAttribute(tgemmS_k<64, 4>,  cudaFuncAttributeMaxDynamicSharedMemorySize, SMSN);

    const dim3 tb(32, 8);
    const dim3 gW(NROWS / 128, 2);    // X@W: BM=128, split-K2 (128 CTAs)
    const dim3 gS(NROWS / 256, 4);    // S-GEMM: BM=256, split-K4 (128 CTAs)

    // ---- fork: split_s16 (S only) runs on a side stream, overlapped with the
    // layer-1 X@W chain (which needs only X/W1). Joined before first S-GEMM.
    cudaStream_t s2;
    cudaStreamCreate(&s2);
    cudaEvent_t eFork, eJoin;
    cudaEventCreateWithFlags(&eFork, cudaEventDisableTiming);
    cudaEventCreateWithFlags(&eJoin, cudaEventDisableTiming);

    cudaEventRecord(eFork, 0);
    cudaStreamWaitEvent(s2, eFork, 0);
    split_s16_k<<<(size_t)NROWS * NROWS / 2048, 256, 0, s2>>>(S, S16);
    cudaEventRecord(eJoin, s2);

    // main stream: layer-1 X@W chain (independent of S16)
    split_k<<<NROWS * 512 / 2048, 256>>>(X, Ahi, Alo);
    convt_k<<<dim3(4, 16), tb>>>(W1, Whi, Wlo, 512, 128);
    tgemm3_k<128, 3><<<gW, 256, SM3W>>>(Ahi, Alo, 512, Whi, Wlo, 512, 512, P);
    combine_t16_k<2><<<dim3(4, 256), tb>>>(P, PSW, Y, B16, NROWS, 128);

    cudaStreamWaitEvent(0, eJoin, 0);   // S16 ready

    // ================= Layer 1 (S-GEMMs) =================
    tgemmS_k<128, 4><<<gS, 512, SMSW>>>(S16, NROWS, B16, NROWS, NROWS, P);
    combine_t16_k<4><<<dim3(4, 256), tb>>>(P, PSW, T, B16, NROWS, 128);
    tgemmS_k<128, 4><<<gS, 512, SMSW>>>(S16, NROWS, B16, NROWS, NROWS, P);
    combine_epi_k<4, true, true><<<NROWS * 128 / 1024, 256>>>(P, PSW, Y, T, h1, b1,
                                                              Z, Ahi, Alo, 127);
    // ================= Layer 2 =================
    convt_k<<<dim3(4, 4), tb>>>(W2, Whi, Wlo, 128, 128);
    tgemm3_k<128, 3><<<gW, 256, SM3W>>>(Ahi, Alo, 128, Whi, Wlo, 128, 128, P);
    combine_t16_k<2><<<dim3(4, 256), tb>>>(P, PSW, Y, B16, NROWS, 128);
    tgemmS_k<128, 4><<<gS, 512, SMSW>>>(S16, NROWS, B16, NROWS, NROWS, P);
    combine_t16_k<4><<<dim3(4, 256), tb>>>(P, PSW, T, B16, NROWS, 128);
    tgemmS_k<128, 4><<<gS, 512, SMSW>>>(S16, NROWS, B16, NROWS, NROWS, P);
    combine_epi_k<4, true, true><<<NROWS * 128 / 1024, 256>>>(P, PSW, Y, T, h2, b2,
                                                              Z, Ahi, Alo, 127);
    // ================= Layer 3 (N=64, no ReLU) =================
    convt_k<<<dim3(2, 4), tb>>>(W3, Whi, Wlo, 128, 64);
    tgemm3_k<64, 4><<<gW, 256, SM3N>>>(Ahi, Alo, 128, Whi, Wlo, 128, 128, P);
    combine_t16_k<2><<<dim3(2, 256), tb>>>(P, PSN, Y, B16, NROWS, 64);
    tgemmS_k<64, 4><<<gS, 512, SMSN>>>(S16, NROWS, B16, NROWS, NROWS, P);
    combine_t16_k<4><<<dim3(2, 256), tb>>>(P, PSN, T, B16, NROWS, 64);
    tgemmS_k<64, 4><<<gS, 512, SMSN>>>(S16, NROWS, B16, NROWS, NROWS, P);
    combine_epi_k<4, false, false><<<NROWS * 64 / 1024, 256>>>(P, PSN, Y, T, h3, b3,
                                                               out, nullptr, nullptr, 63);
}

// round 17
// speedup vs baseline: 1.2637x; 1.0171x over previous
#include <cuda_runtime.h>
#include <cuda_bf16.h>
#include <cuda_fp16.h>
#include <cstdint>

#define NROWS 8192

// ---------------- scratch (__device__ globals; no allocation allowed) ----------
__device__ __align__(16) float g_Y[NROWS * 128];
__device__ __align__(16) float g_T[NROWS * 128];
__device__ __align__(16) float g_Z[NROWS * 128];
__device__ __align__(16) float g_P[4 * NROWS * 128];                  // split-K partials (16 MB)
__device__ __align__(16) __half g_S16[(size_t)NROWS * NROWS];         // fp16(S), 128 MB
__device__ __align__(16) __half g_A16[NROWS * 512];                   // row-major acts fp16
__device__ __align__(16) __half g_B16[128 * NROWS];                   // transposed acts fp16
__device__ __align__(16) __half g_W16[128 * 512];                     // transposed weights fp16

__device__ __forceinline__ uint32_t smem_u32(const void* p) {
    uint32_t a;
    asm("{ .reg .u64 t; cvta.to.shared.u64 t, %1; cvt.u32.u64 %0, t; }" : "=r"(a) : "l"(p));
    return a;
}

#define LDSM_X4(r, addr)                                                        \
    asm volatile("ldmatrix.sync.aligned.m8n8.x4.shared.b16 {%0,%1,%2,%3}, [%4];"\
                 : "=r"((r)[0]), "=r"((r)[1]), "=r"((r)[2]), "=r"((r)[3])       \
                 : "r"(addr))

#define MMA_FP16(d, a, b)                                                       \
    asm volatile("mma.sync.aligned.m16n8k16.row.col.f32.f16.f16.f32 "           \
                 "{%0,%1,%2,%3}, {%4,%5,%6,%7}, {%8,%9}, {%0,%1,%2,%3};"        \
                 : "+f"((d)[0]), "+f"((d)[1]), "+f"((d)[2]), "+f"((d)[3])       \
                 : "r"((a)[0]), "r"((a)[1]), "r"((a)[2]), "r"((a)[3]),          \
                   "r"((b)[0]), "r"((b)[1]))

#define CP16(s, g)                                                              \
    asm volatile("cp.async.cg.shared.global [%0], [%1], 16;"                    \
                 :: "r"(s), "l"(g) : "memory")
#define CP_COMMIT() asm volatile("cp.async.commit_group;" ::: "memory")
#define CP_WAIT(n)  asm volatile("cp.async.wait_group %0;" :: "n"(n) : "memory")

// ---------------- fp32 -> fp16 row-major convert (S and X) ---------------------
__global__ void conv16_k(const float* __restrict__ in, __half* __restrict__ o)
{
    size_t i = ((size_t)blockIdx.x * 256 + threadIdx.x) * 8;
    float4 v0 = *(const float4*)(in + i);
    float4 v1 = *(const float4*)(in + i + 4);
    __half2 h[4];
    h[0] = __floats2half2_rn(v0.x, v0.y);
    h[1] = __floats2half2_rn(v0.z, v0.w);
    h[2] = __floats2half2_rn(v1.x, v1.y);
    h[3] = __floats2half2_rn(v1.z, v1.w);
    *(uint4*)(o + i) = *reinterpret_cast<uint4*>(h);
}

// ---------------- transpose + fp16 convert (for W) -----------------------------
// in: [R rows][C cols] fp32;  out: [C][R] fp16
__global__ void convt16_k(const float* __restrict__ in, __half* __restrict__ o16,
                          int R, int C)
{
    __shared__ float tile[32][33];
    const int bx = blockIdx.x * 32, by = blockIdx.y * 32;
    const int tx = threadIdx.x, ty = threadIdx.y;
#pragma unroll
    for (int i = 0; i < 32; i += 8)
        tile[ty + i][tx] = in[(size_t)(by + ty + i) * C + bx + tx];
    __syncthreads();
#pragma unroll
    for (int i = 0; i < 32; i += 8) {
        float v = tile[tx][ty + i];
        o16[(size_t)(bx + ty + i) * R + by + tx] = __float2half(v);
    }
}

// ---------------- combine NP split-K partials + transpose fp16 convert ---------
template <int NP>
__global__ void combine_t16_k(const float* __restrict__ P, size_t pstride,
                              float* __restrict__ Trm,
                              __half* __restrict__ o16, int R, int C)
{
    __shared__ float tile[32][33];
    const int bx = blockIdx.x * 32, by = blockIdx.y * 32;
    const int tx = threadIdx.x, ty = threadIdx.y;
#pragma unroll
    for (int i = 0; i < 32; i += 8) {
        size_t idx = (size_t)(by + ty + i) * C + bx + tx;
        float v = 0.f;
#pragma unroll
        for (int p = 0; p < NP; p++) v += P[idx + p * pstride];
        Trm[idx] = v;
        tile[ty + i][tx] = v;
    }
    __syncthreads();
#pragma unroll
    for (int i = 0; i < 32; i += 8) {
        float v = tile[tx][ty + i];
        o16[(size_t)(bx + ty + i) * R + by + tx] = __float2half(v);
    }
}

// ---------------- combine NP partials + poly epilogue (+optional fp16 out) -----
template <int NP, bool RELU, bool W16OUT>
__global__ void combine_epi_k(const float* __restrict__ P, size_t pstride,
                              const float* __restrict__ Y, const float* __restrict__ T,
                              const float* __restrict__ hv, const float* __restrict__ bias,
                              float* __restrict__ Z, __half* __restrict__ z16,
                              int nmask)
{
    const size_t i = ((size_t)blockIdx.x * 256 + threadIdx.x) * 4;
    const float c0 = hv[0], c1 = hv[1], c2 = hv[2];
    float4 s = *(const float4*)(P + i);
#pragma unroll
    for (int p = 1; p < NP; p++) {
        const float4 q = *(const float4*)(P + i + p * pstride);
        s.x += q.x; s.y += q.y; s.z += q.z; s.w += q.w;
    }
    const float4 y  = *(const float4*)(Y + i);
    const float4 t  = *(const float4*)(T + i);
    const float4 bb = *(const float4*)(bias + (i & nmask));
    float4 v;
    v.x = c0 * y.x + c1 * t.x + c2 * s.x + bb.x;
    v.y = c0 * y.y + c1 * t.y + c2 * s.y + bb.y;
    v.z = c0 * y.z + c1 * t.z + c2 * s.z + bb.z;
    v.w = c0 * y.w + c1 * t.w + c2 * s.w + bb.w;
    if (RELU) {
        v.x = fmaxf(v.x, 0.f); v.y = fmaxf(v.y, 0.f);
        v.z = fmaxf(v.z, 0.f); v.w = fmaxf(v.w, 0.f);
    }
    *(float4*)(Z + i) = v;
    if (W16OUT) {
        __half2 h[2];
        h[0] = __floats2half2_rn(v.x, v.y);
        h[1] = __floats2half2_rn(v.z, v.w);
        *(uint2*)(z16 + i) = *reinterpret_cast<uint2*>(h);
    }
}

// ================== fp16 1-pass GEMM: BM=256, 512 thr (16 warps, 4m x 4n) ======
// C_partial[by] = A16[M, kslice] x B16t[BN, kslice]; partial stride gridDim.x*256*BN
template <int BN, int D>
__global__ void __launch_bounds__(512)
tgemmS_k(const __half* __restrict__ A16, int lda,
         const __half* __restrict__ B16, int ldb, int Ktot, float* __restrict__ C)
{
    extern __shared__ char sm[];
    constexpr int WN = BN / 4;          // warp n extent (32 or 16)
    constexpr int NT = WN / 8;          // 4 or 2
    constexpr int ASPL = 256 * 128;     // A: 256 rows x 128B fp16
    constexpr int BSPL = BN * 128;      // B: BN rows x 128B fp16
    constexpr int STAGE = ASPL + BSPL;

    const int tid = threadIdx.x, wid = tid >> 5, lid = tid & 31;
    const int wm = wid & 3, wn = wid >> 2;     // 4 m-warps x 4 n-warps
    const int m0 = blockIdx.x * 256;
    const int kslice = Ktot / gridDim.y;
    const int kbase = blockIdx.y * kslice;
    const int nk = kslice / 64;
    float* Cout = C + (size_t)blockIdx.y * (gridDim.x * 256) * BN;
    const uint32_t smb = smem_u32(sm);

    const int ldrow = tid >> 3, ldc = tid & 7;  // ldrow in 0..63
    const int arl = lid & 15, ahf = lid >> 4;
    const int brl = (lid & 7) + ((lid >> 4) << 3);
    const int bhf = (lid >> 3) & 1;
    const int asw = arl & 7, bsw = lid & 7;

    float acc[4][NT][4];                // warp tile 64 x WN
#pragma unroll
    for (int mt = 0; mt < 4; mt++)
#pragma unroll
        for (int nt = 0; nt < NT; nt++)
#pragma unroll
            for (int j = 0; j < 4; j++) acc[mt][nt][j] = 0.f;

    auto issue = [&](int ch, int buf) {
        const uint32_t sb = smb + buf * STAGE;
        const int kg = kbase + ch * 64;
#pragma unroll
        for (int it = 0; it < 4; it++) {               // A: 256 rows fp16
            const int row = ldrow + 64 * it;
            const size_t go = (size_t)(m0 + row) * lda + kg + ldc * 8;
            const uint32_t so = sb + row * 128 + ((ldc ^ (row & 7)) << 4);
            CP16(so, (const void*)(A16 + go));
        }
#pragma unroll
        for (int it = 0; it < BN / 64; it++) {         // B: single fp16
            const int row = ldrow + 64 * it;
            const size_t go = (size_t)row * ldb + kg + ldc * 8;
            const uint32_t so = sb + ASPL + row * 128 + ((ldc ^ (row & 7)) << 4);
            CP16(so, (const void*)(B16 + go));
        }
    };

#pragma unroll
    for (int s = 0; s < D - 1; s++) {
        if (s < nk) issue(s, s);
        CP_COMMIT();
    }

    for (int i = 0; i < nk; i++) {
        CP_WAIT(D - 2);
        __syncthreads();
        if (i + D - 1 < nk) issue(i + D - 1, (i + D - 1) % D);
        CP_COMMIT();

        const uint32_t cab = smb + (i % D) * STAGE;
        const uint32_t cbb = cab + ASPL;

#pragma unroll
        for (int ks = 0; ks < 4; ks++) {
            uint32_t bH[NT][2];
#pragma unroll
            for (int p = 0; p < NT / 2; p++) {
                const uint32_t bo = (uint32_t)((wn * WN + p * 16 + brl) * 128)
                                  + (uint32_t)(((ks * 2 + bhf) ^ bsw) << 4);
                uint32_t t[4];
                LDSM_X4(t, cbb + bo);
                bH[2 * p][0] = t[0]; bH[2 * p][1] = t[1];
                bH[2 * p + 1][0] = t[2]; bH[2 * p + 1][1] = t[3];
            }
            uint32_t aF[4][4];
#pragma unroll
            for (int mt = 0; mt < 4; mt++) {
                const uint32_t ao = (uint32_t)((wm * 64 + mt * 16 + arl) * 128)
                                  + (uint32_t)(((ks * 2 + ahf) ^ asw) << 4);
                LDSM_X4(aF[mt], cab + ao);
            }
#pragma unroll
            for (int mt = 0; mt < 4; mt++)
#pragma unroll
                for (int nt = 0; nt < NT; nt++)
                    MMA_FP16(acc[mt][nt], aF[mt], bH[nt]);
        }
    }

    // ---- write partial tile ----
#pragma unroll
    for (int mt = 0; mt < 4; mt++)
#pragma unroll
        for (int half = 0; half < 2; half++) {
            const int row = m0 + wm * 64 + mt * 16 + (lid >> 2) + half * 8;
#pragma unroll
            for (int nt = 0; nt < NT; nt++) {
                const int col = wn * WN + nt * 8 + (lid & 3) * 2;
                float2 v = make_float2(acc[mt][nt][half * 2 + 0],
                                       acc[mt][nt][half * 2 + 1]);
                *(float2*)(Cout + (size_t)row * BN + col) = v;
            }
        }
}

// -------------------------------------------------------------------------------
extern "C" void kernel_launch(void* const* d_in, const int* in_sizes, int n_in,
                              void* d_out, int out_size)
{
    (void)in_sizes; (void)n_in; (void)out_size;
    const float* S  = (const float*)d_in[0];
    const float* X  = (const float*)d_in[1];
    const float* W1 = (const float*)d_in[2];
    const float* h1 = (const float*)d_in[3];
    const float* b1 = (const float*)d_in[4];
    const float* W2 = (const float*)d_in[5];
    const float* h2 = (const float*)d_in[6];
    const float* b2 = (const float*)d_in[7];
    const float* W3 = (const float*)d_in[8];
    const float* h3 = (const float*)d_in[9];
    const float* b3 = (const float*)d_in[10];
    float* out = (float*)d_out;

    float *Y, *T, *Z, *P;
    __half *S16, *A16, *B16, *W16;
    cudaGetSymbolAddress((void**)&Y, g_Y);
    cudaGetSymbolAddress((void**)&T, g_T);
    cudaGetSymbolAddress((void**)&Z, g_Z);
    cudaGetSymbolAddress((void**)&P, g_P);
    cudaGetSymbolAddress((void**)&S16, g_S16);
    cudaGetSymbolAddress((void**)&A16, g_A16);
    cudaGetSymbolAddress((void**)&B16, g_B16);
    cudaGetSymbolAddress((void**)&W16, g_W16);

    const size_t PSW = (size_t)NROWS * 128;   // partial stride, BN=128
    const size_t PSN = (size_t)NROWS * 64;    // partial stride, BN=64

    const int SMSW = 4 * (32768 + 16384);     // 196608: BN=128, D=4
    const int SMSN = 4 * (32768 + 8192);      // 163840: BN=64,  D=4
    cudaFuncSetAttribute(tgemmS_k<128, 4>, cudaFuncAttributeMaxDynamicSharedMemorySize, SMSW);
    cudaFuncSetAttribute(tgemmS_k<64, 4>,  cudaFuncAttributeMaxDynamicSharedMemorySize, SMSN);

    const dim3 tb(32, 8);
    const dim3 gS(NROWS / 256, 4);    // S-GEMM: split-K4 (128 CTAs)
    const dim3 gW4(NROWS / 256, 4);   // X@W1: K=512, split-K4 (kslice 128)
    const dim3 gW2(NROWS / 256, 2);   // X@W2/3: K=128, split-K2 (kslice 64)

    // one-time converts
    conv16_k<<<(size_t)NROWS * NROWS / 2048, 256>>>(S, S16);
    conv16_k<<<NROWS * 512 / 2048, 256>>>(X, A16);

    // ================= Layer 1 (in=512, out=128) =================
    convt16_k<<<dim3(4, 16), tb>>>(W1, W16, 512, 128);
    tgemmS_k<128, 4><<<gW4, 512, SMSW>>>(A16, 512, W16, 512, 512, P);
    combine_t16_k<4><<<dim3(4, 256), tb>>>(P, PSW, Y, B16, NROWS, 128);
    tgemmS_k<128, 4><<<gS, 512, SMSW>>>(S16, NROWS, B16, NROWS, NROWS, P);
    combine_t16_k<4><<<dim3(4, 256), tb>>>(P, PSW, T, B16, NROWS, 128);
    tgemmS_k<128, 4><<<gS, 512, SMSW>>>(S16, NROWS, B16, NROWS, NROWS, P);
    combine_epi_k<4, true, true><<<NROWS * 128 / 1024, 256>>>(P, PSW, Y, T, h1, b1,
                                                              Z, A16, 127);
    // ================= Layer 2 (128 -> 128) =================
    convt16_k<<<dim3(4, 4), tb>>>(W2, W16, 128, 128);
    tgemmS_k<128, 4><<<gW2, 512, SMSW>>>(A16, 128, W16, 128, 128, P);
    combine_t16_k<2><<<dim3(4, 256), tb>>>(P, PSW, Y, B16, NROWS, 128);
    tgemmS_k<128, 4><<<gS, 512, SMSW>>>(S16, NROWS, B16, NROWS, NROWS, P);
    combine_t16_k<4><<<dim3(4, 256), tb>>>(P, PSW, T, B16, NROWS, 128);
    tgemmS_k<128, 4><<<gS, 512, SMSW>>>(S16, NROWS, B16, NROWS, NROWS, P);
    combine_epi_k<4, true, true><<<NROWS * 128 / 1024, 256>>>(P, PSW, Y, T, h2, b2,
                                                              Z, A16, 127);
    // ================= Layer 3 (128 -> 64, no ReLU) =================
    convt16_k<<<dim3(2, 4), tb>>>(W3, W16, 128, 64);
    tgemmS_k<64, 4><<<gW2, 512, SMSN>>>(A16, 128, W16, 128, 128, P);
    combine_t16_k<2><<<dim3(2, 256), tb>>>(P, PSN, Y, B16, NROWS, 64);
    tgemmS_k<64, 4><<<gS, 512, SMSN>>>(S16, NROWS, B16, NROWS, NROWS, P);
    combine_t16_k<4><<<dim3(2, 256), tb>>>(P, PSN, T, B16, NROWS, 64);
    tgemmS_k<64, 4><<<gS, 512, SMSN>>>(S16, NROWS, B16, NROWS, NROWS, P);
    combine_epi_k<4, false, false><<<NROWS * 64 / 1024, 256>>>(P, PSN, Y, T, h3, b3,
                                                               out, nullptr, 63);
}